// round 1
// baseline (speedup 1.0000x reference)
#include <cuda_runtime.h>
#include <math.h>

#define TT    64
#define BB    2048
#define LAT   128
#define OBSD  128
#define CTRL  16
#define NMATD 16
#define HH    128

// ---------------- scratch (no allocation allowed) ----------------
__device__ float g_h0[BB * HH];
__device__ float g_h1[BB * HH];
__device__ float g_c[BB * HH];
__device__ float g_hbuf[BB * HH];
__device__ float g_rbuf[BB * HH];
__device__ float g_wbuf[BB * LAT];
__device__ float g_w1[BB * LAT];
__device__ float g_alpha[BB * NMATD];
__device__ float g_P[BB * NMATD * LAT];          // 2048 x 2048
__device__ float g_Wstack[256 * 4 * HH];         // permuted [Wx;Wh], cols j*4+gate
__device__ float g_bstack[4 * HH];
__device__ float g_Mbig[272 * NMATD * LAT];      // rows c in [z|u|w], cols i*128+j

// ---------------- weight prep ----------------
__global__ void build_wstack(const float* __restrict__ Wx,
                             const float* __restrict__ Wh,
                             const float* __restrict__ b) {
    int idx = blockIdx.x * blockDim.x + threadIdx.x;
    if (idx < 256 * 512) {
        int row = idx / 512, cp = idx % 512;
        int j = cp >> 2, g = cp & 3;          // permuted col = j*4+g
        int orig = g * 128 + j;               // flax gate order i,f,g,o
        float v = (row < 128) ? Wx[row * 512 + orig] : Wh[(row - 128) * 512 + orig];
        g_Wstack[row * 512 + cp] = v;
    }
    if (idx < 512) {
        int j = idx >> 2, g = idx & 3;
        g_bstack[idx] = b[g * 128 + j];
    }
}

__global__ void build_mbig(const float* __restrict__ A,
                           const float* __restrict__ Bm,
                           const float* __restrict__ C) {
    int idx = blockIdx.x * blockDim.x + threadIdx.x;
    if (idx >= 272 * 2048) return;
    int c = idx / 2048, n = idx % 2048;
    int i = n >> 7, j = n & 127;
    float v;
    if (c < 128)       v = A[i * 128 * 128 + j * 128 + c];
    else if (c < 144)  v = Bm[i * 128 * 16 + j * 16 + (c - 128)];
    else               v = C[i * 128 * 128 + j * 128 + (c - 144)];
    g_Mbig[idx] = v;
}

// ---------------- generic GEMM with 3-way concat A operand ----------------
// out[M,N] = act(cat(s0|s1|s2)[M,K] @ W[K,N] + bias). All widths multiples of 16,
// M multiple of 64, N multiple of 64, K multiple of 16.
template <int ACT, bool BIAS>
__global__ __launch_bounds__(256) void gemm3(
    const float* __restrict__ s0, int w0,
    const float* __restrict__ s1, int w1,
    const float* __restrict__ s2, int w2,
    const float* __restrict__ W, const float* __restrict__ bias,
    float* __restrict__ out, int M, int N, int K) {
    __shared__ float As[16][68];
    __shared__ float Ws[16][64];
    const int tid = threadIdx.x;
    const int m0 = blockIdx.x * 64, n0 = blockIdx.y * 64;
    const int ar = tid >> 2, ac = (tid & 3) << 2;
    const int wr = tid >> 4, wc = (tid & 15) << 2;
    const int tm = (tid >> 4) << 2, tn = (tid & 15) << 2;
    float acc[4][4] = {};
    for (int k0 = 0; k0 < K; k0 += 16) {
        const float* ap; int aw, ak;
        if (k0 < w0)            { ap = s0; aw = w0; ak = k0; }
        else if (k0 < w0 + w1)  { ap = s1; aw = w1; ak = k0 - w0; }
        else                    { ap = s2; aw = w2; ak = k0 - w0 - w1; }
        float4 av = *reinterpret_cast<const float4*>(ap + (size_t)(m0 + ar) * aw + ak + ac);
        As[ac + 0][ar] = av.x; As[ac + 1][ar] = av.y;
        As[ac + 2][ar] = av.z; As[ac + 3][ar] = av.w;
        *reinterpret_cast<float4*>(&Ws[wr][wc]) =
            *reinterpret_cast<const float4*>(W + (size_t)(k0 + wr) * N + n0 + wc);
        __syncthreads();
#pragma unroll
        for (int k = 0; k < 16; k++) {
            float a0 = As[k][tm], a1 = As[k][tm + 1], a2 = As[k][tm + 2], a3 = As[k][tm + 3];
            float4 bv = *reinterpret_cast<float4*>(&Ws[k][tn]);
            acc[0][0] += a0 * bv.x; acc[0][1] += a0 * bv.y; acc[0][2] += a0 * bv.z; acc[0][3] += a0 * bv.w;
            acc[1][0] += a1 * bv.x; acc[1][1] += a1 * bv.y; acc[1][2] += a1 * bv.z; acc[1][3] += a1 * bv.w;
            acc[2][0] += a2 * bv.x; acc[2][1] += a2 * bv.y; acc[2][2] += a2 * bv.z; acc[2][3] += a2 * bv.w;
            acc[3][0] += a3 * bv.x; acc[3][1] += a3 * bv.y; acc[3][2] += a3 * bv.z; acc[3][3] += a3 * bv.w;
        }
        __syncthreads();
    }
#pragma unroll
    for (int i = 0; i < 4; i++) {
        int m = m0 + tm + i;
#pragma unroll
        for (int j = 0; j < 4; j++) {
            int n = n0 + tn + j;
            float v = acc[i][j];
            if (BIAS) v += bias[n];
            if (ACT == 1) v = fmaxf(v, 0.f);
            out[(size_t)m * N + n] = v;
        }
    }
}

// ---------------- gauss GEMM: out = mean + exp(logvar/2)*eps ----------------
// W is K x 256 (first 128 cols mean, last 128 logvar). out is M x 128.
__global__ __launch_bounds__(256) void gemm_gauss(
    const float* __restrict__ Ain, int K,
    const float* __restrict__ W, const float* __restrict__ bias,
    const float* __restrict__ eps, float* __restrict__ out, int M) {
    __shared__ float As[16][68];
    __shared__ float W1s[16][64];
    __shared__ float W2s[16][64];
    const int tid = threadIdx.x;
    const int m0 = blockIdx.x * 64, n0 = blockIdx.y * 64;
    const int ar = tid >> 2, ac = (tid & 3) << 2;
    const int wr = tid >> 4, wc = (tid & 15) << 2;
    const int tm = (tid >> 4) << 2, tn = (tid & 15) << 2;
    float acc1[4][4] = {}, acc2[4][4] = {};
    for (int k0 = 0; k0 < K; k0 += 16) {
        float4 av = *reinterpret_cast<const float4*>(Ain + (size_t)(m0 + ar) * K + k0 + ac);
        As[ac + 0][ar] = av.x; As[ac + 1][ar] = av.y;
        As[ac + 2][ar] = av.z; As[ac + 3][ar] = av.w;
        *reinterpret_cast<float4*>(&W1s[wr][wc]) =
            *reinterpret_cast<const float4*>(W + (size_t)(k0 + wr) * 256 + n0 + wc);
        *reinterpret_cast<float4*>(&W2s[wr][wc]) =
            *reinterpret_cast<const float4*>(W + (size_t)(k0 + wr) * 256 + 128 + n0 + wc);
        __syncthreads();
#pragma unroll
        for (int k = 0; k < 16; k++) {
            float a0 = As[k][tm], a1 = As[k][tm + 1], a2 = As[k][tm + 2], a3 = As[k][tm + 3];
            float4 b1 = *reinterpret_cast<float4*>(&W1s[k][tn]);
            float4 b2 = *reinterpret_cast<float4*>(&W2s[k][tn]);
            acc1[0][0] += a0 * b1.x; acc1[0][1] += a0 * b1.y; acc1[0][2] += a0 * b1.z; acc1[0][3] += a0 * b1.w;
            acc1[1][0] += a1 * b1.x; acc1[1][1] += a1 * b1.y; acc1[1][2] += a1 * b1.z; acc1[1][3] += a1 * b1.w;
            acc1[2][0] += a2 * b1.x; acc1[2][1] += a2 * b1.y; acc1[2][2] += a2 * b1.z; acc1[2][3] += a2 * b1.w;
            acc1[3][0] += a3 * b1.x; acc1[3][1] += a3 * b1.y; acc1[3][2] += a3 * b1.z; acc1[3][3] += a3 * b1.w;
            acc2[0][0] += a0 * b2.x; acc2[0][1] += a0 * b2.y; acc2[0][2] += a0 * b2.z; acc2[0][3] += a0 * b2.w;
            acc2[1][0] += a1 * b2.x; acc2[1][1] += a1 * b2.y; acc2[1][2] += a1 * b2.z; acc2[1][3] += a1 * b2.w;
            acc2[2][0] += a2 * b2.x; acc2[2][1] += a2 * b2.y; acc2[2][2] += a2 * b2.z; acc2[2][3] += a2 * b2.w;
            acc2[3][0] += a3 * b2.x; acc2[3][1] += a3 * b2.y; acc2[3][2] += a3 * b2.z; acc2[3][3] += a3 * b2.w;
        }
        __syncthreads();
    }
#pragma unroll
    for (int i = 0; i < 4; i++) {
        int m = m0 + tm + i;
#pragma unroll
        for (int j = 0; j < 4; j++) {
            int n = n0 + tn + j;
            float mean = acc1[i][j] + bias[n];
            float lv   = acc2[i][j] + bias[128 + n];
            out[(size_t)m * 128 + n] = mean + expf(0.5f * lv) * eps[(size_t)m * 128 + n];
        }
    }
}

// ---------------- LSTM step: gates GEMM + fused cell update ----------------
// A = cat(x_t[128], h_in[128]); W = permuted Wstack (256x512). Each thread's
// 4 cols = (i,f,g,o) of one hidden unit j.
__global__ __launch_bounds__(256) void gemm_lstm(
    const float* __restrict__ x, const float* __restrict__ hin,
    float* __restrict__ c, float* __restrict__ hout) {
    __shared__ float As[16][68];
    __shared__ float Ws[16][64];
    const int tid = threadIdx.x;
    const int m0 = blockIdx.x * 64, n0 = blockIdx.y * 64;
    const int ar = tid >> 2, ac = (tid & 3) << 2;
    const int wr = tid >> 4, wc = (tid & 15) << 2;
    const int tm = (tid >> 4) << 2, tn = (tid & 15) << 2;
    float acc[4][4] = {};
    for (int k0 = 0; k0 < 256; k0 += 16) {
        const float* ap = (k0 < 128) ? x : hin;
        int ak = (k0 < 128) ? k0 : k0 - 128;
        float4 av = *reinterpret_cast<const float4*>(ap + (size_t)(m0 + ar) * 128 + ak + ac);
        As[ac + 0][ar] = av.x; As[ac + 1][ar] = av.y;
        As[ac + 2][ar] = av.z; As[ac + 3][ar] = av.w;
        *reinterpret_cast<float4*>(&Ws[wr][wc]) =
            *reinterpret_cast<const float4*>(g_Wstack + (size_t)(k0 + wr) * 512 + n0 + wc);
        __syncthreads();
#pragma unroll
        for (int k = 0; k < 16; k++) {
            float a0 = As[k][tm], a1 = As[k][tm + 1], a2 = As[k][tm + 2], a3 = As[k][tm + 3];
            float4 bv = *reinterpret_cast<float4*>(&Ws[k][tn]);
            acc[0][0] += a0 * bv.x; acc[0][1] += a0 * bv.y; acc[0][2] += a0 * bv.z; acc[0][3] += a0 * bv.w;
            acc[1][0] += a1 * bv.x; acc[1][1] += a1 * bv.y; acc[1][2] += a1 * bv.z; acc[1][3] += a1 * bv.w;
            acc[2][0] += a2 * bv.x; acc[2][1] += a2 * bv.y; acc[2][2] += a2 * bv.z; acc[2][3] += a2 * bv.w;
            acc[3][0] += a3 * bv.x; acc[3][1] += a3 * bv.y; acc[3][2] += a3 * bv.z; acc[3][3] += a3 * bv.w;
        }
        __syncthreads();
    }
    const int j = (n0 + tn) >> 2;
    float b0 = g_bstack[n0 + tn + 0], b1 = g_bstack[n0 + tn + 1];
    float b2 = g_bstack[n0 + tn + 2], b3 = g_bstack[n0 + tn + 3];
#pragma unroll
    for (int i = 0; i < 4; i++) {
        int b = m0 + tm + i;
        float gi = acc[i][0] + b0;
        float gf = acc[i][1] + b1;
        float gg = acc[i][2] + b2;
        float go = acc[i][3] + b3;
        float si = 1.f / (1.f + expf(-gi));
        float sf = 1.f / (1.f + expf(-gf));
        float so = 1.f / (1.f + expf(-go));
        size_t idx = (size_t)b * 128 + j;
        float cn = sf * c[idx] + si * tanhf(gg);
        c[idx] = cn;
        hout[idx] = so * tanhf(cn);
    }
}

// ---------------- alpha logits + softmax (N=16) ----------------
__global__ __launch_bounds__(256) void alpha_kernel(
    const float* __restrict__ z, const float* __restrict__ u,
    const float* __restrict__ aW, float* __restrict__ alpha) {
    __shared__ float sW[144][16];
    __shared__ float sl[16][16];
    __shared__ float se[16][16];
    const int tid = threadIdx.x;
    for (int idx = tid; idx < 144 * 16; idx += 256)
        sW[idx / 16][idx % 16] = aW[idx];
    __syncthreads();
    const int br = tid >> 4, i = tid & 15;
    const int b = blockIdx.x * 16 + br;
    const float* zb = z + (size_t)b * 128;
    const float* ub = u + (size_t)b * 16;
    float acc = 0.f;
#pragma unroll 8
    for (int k = 0; k < 128; k++) acc += zb[k] * sW[k][i];
#pragma unroll
    for (int k = 0; k < 16; k++) acc += ub[k] * sW[128 + k][i];
    sl[br][i] = acc;
    __syncthreads();
    float mx = -1e30f;
#pragma unroll
    for (int q = 0; q < 16; q++) mx = fmaxf(mx, sl[br][q]);
    float e = expf(acc - mx);
    se[br][i] = e;
    __syncthreads();
    float s = 0.f;
#pragma unroll
    for (int q = 0; q < 16; q++) s += se[br][q];
    alpha[(size_t)b * 16 + i] = e / s;
}

// ---------------- z_next = sum_i alpha[b,i] * P[b, i*128+j] ----------------
__global__ __launch_bounds__(256) void mix_reduce(
    const float* __restrict__ P, const float* __restrict__ alpha,
    float* __restrict__ znext) {
    int idx = blockIdx.x * 256 + threadIdx.x;   // B*128 total
    int b = idx >> 7, j = idx & 127;
    const float* pb = P + (size_t)b * 2048 + j;
    const float* ab = alpha + (size_t)b * 16;
    float s = 0.f;
#pragma unroll
    for (int i = 0; i < 16; i++) s += ab[i] * pb[i * 128];
    znext[idx] = s;
}

// ---------------- host orchestration ----------------
extern "C" void kernel_launch(void* const* d_in, const int* in_sizes, int n_in,
                              void* d_out, int out_size) {
    const float* xs      = (const float*)d_in[0];
    const float* us      = (const float*)d_in[1];
    const float* eps1    = (const float*)d_in[2];
    const float* eps     = (const float*)d_in[3];
    const float* lstm_Wx = (const float*)d_in[4];
    const float* lstm_Wh = (const float*)d_in[5];
    const float* lstm_b  = (const float*)d_in[6];
    const float* init_W1 = (const float*)d_in[7];
    const float* init_b1 = (const float*)d_in[8];
    const float* init_W2 = (const float*)d_in[9];
    const float* init_b2 = (const float*)d_in[10];
    const float* trans_W1= (const float*)d_in[11];
    const float* trans_b1= (const float*)d_in[12];
    const float* trans_W2= (const float*)d_in[13];
    const float* trans_b2= (const float*)d_in[14];
    const float* obs_W1  = (const float*)d_in[15];
    const float* obs_b1  = (const float*)d_in[16];
    const float* obs_W2  = (const float*)d_in[17];
    const float* obs_b2  = (const float*)d_in[18];
    const float* rec_W1  = (const float*)d_in[19];
    const float* rec_b1  = (const float*)d_in[20];
    const float* rec_W2  = (const float*)d_in[21];
    const float* rec_b2  = (const float*)d_in[22];
    const float* alpha_W = (const float*)d_in[23];
    const float* Abank   = (const float*)d_in[24];
    const float* Bbank   = (const float*)d_in[25];
    const float* Cbank   = (const float*)d_in[26];

    float *h0, *h1, *c, *hbuf, *rbuf, *wbuf, *w1buf, *alphaB, *P, *Mbig;
    cudaGetSymbolAddress((void**)&h0, g_h0);
    cudaGetSymbolAddress((void**)&h1, g_h1);
    cudaGetSymbolAddress((void**)&c, g_c);
    cudaGetSymbolAddress((void**)&hbuf, g_hbuf);
    cudaGetSymbolAddress((void**)&rbuf, g_rbuf);
    cudaGetSymbolAddress((void**)&wbuf, g_wbuf);
    cudaGetSymbolAddress((void**)&w1buf, g_w1);
    cudaGetSymbolAddress((void**)&alphaB, g_alpha);
    cudaGetSymbolAddress((void**)&P, g_P);
    cudaGetSymbolAddress((void**)&Mbig, g_Mbig);

    cudaMemsetAsync(h0, 0, sizeof(float) * BB * HH);
    cudaMemsetAsync(c, 0, sizeof(float) * BB * HH);

    build_wstack<<<(256 * 512 + 255) / 256, 256>>>(lstm_Wx, lstm_Wh, lstm_b);
    build_mbig<<<(272 * 2048 + 255) / 256, 256>>>(Abank, Bbank, Cbank);

    // LSTM over T (ping-pong h)
    dim3 gLSTM(BB / 64, 512 / 64);
    for (int t = 0; t < TT; t++) {
        const float* hin = (t & 1) ? h1 : h0;
        float* hout      = (t & 1) ? h0 : h1;
        gemm_lstm<<<gLSTM, 256>>>(xs + (size_t)t * BB * OBSD, hin, c, hout);
    }
    float* hfin = h0;  // t=63 (odd) wrote h0

    float* zs   = (float*)d_out;
    float* xrec = zs + (size_t)TT * BB * LAT;

    dim3 g128(BB / 64, 2);
    // init network
    gemm3<1, true><<<g128, 256>>>(hfin, 128, nullptr, 0, nullptr, 0,
                                  init_W1, init_b1, hbuf, BB, 128, 128);
    gemm_gauss<<<g128, 256>>>(hbuf, 128, init_W2, init_b2, eps1, w1buf, BB);
    gemm3<1, true><<<g128, 256>>>(w1buf, 128, nullptr, 0, nullptr, 0,
                                  trans_W1, trans_b1, hbuf, BB, 128, 128);
    gemm3<0, true><<<g128, 256>>>(hbuf, 128, nullptr, 0, nullptr, 0,
                                  trans_W2, trans_b2, zs, BB, 128, 128);

    dim3 gMix(BB / 64, 2048 / 64);
    for (int t = 0; t < TT - 1; t++) {
        const float* z  = zs + (size_t)t * BB * LAT;
        float* zn       = zs + (size_t)(t + 1) * BB * LAT;
        float* xr       = xrec + (size_t)t * BB * OBSD;
        const float* xt1 = xs + (size_t)(t + 1) * BB * OBSD;
        const float* ut  = us + (size_t)t * BB * CTRL;
        // observation: x_mean from current z
        gemm3<1, true><<<g128, 256>>>(z, 128, nullptr, 0, nullptr, 0,
                                      obs_W1, obs_b1, hbuf, BB, 128, 128);
        gemm3<0, true><<<g128, 256>>>(hbuf, 128, nullptr, 0, nullptr, 0,
                                      obs_W2, obs_b2, xr, BB, 128, 128);
        // recognition: r = relu([z,x_next,u] @ rec_W1 + b1); w = mean+exp(lv/2)*eps
        gemm3<1, true><<<g128, 256>>>(z, 128, xt1, 128, ut, 16,
                                      rec_W1, rec_b1, rbuf, BB, 128, 272);
        gemm_gauss<<<g128, 256>>>(rbuf, 128, rec_W2, rec_b2,
                                  eps + (size_t)t * BB * LAT, wbuf, BB);
        // alphas
        alpha_kernel<<<BB / 16, 256>>>(z, ut, alpha_W, alphaB);
        // P = [z,u,w] @ Mbig ; z_next = alpha-weighted reduce
        gemm3<0, false><<<gMix, 256>>>(z, 128, ut, 16, wbuf, 128,
                                       Mbig, nullptr, P, BB, 2048, 272);
        mix_reduce<<<BB * 128 / 256, 256>>>(P, alphaB, zn);
    }
}